// round 13
// baseline (speedup 1.0000x reference)
#include <cuda_runtime.h>
#include <cstdint>

// soft_to_hard_quantize via fp16 tensor cores (mma.m16n8k16).
// R13 vs R12 (same math, fewer issue slots):
//  - softmax denominator computed by an extra ones-column MMA (exact f32 sum of
//    the SAME rounded fp16 weights -> consistency preserved)
//  - float4 x loads via k-slot permutation (codebook permuted to match)
//  - float4 stores via output-column permutation baked into the pass-2 table
//
// logit[v][m] = 14.4269504*dot(x_v, r_m) - 7.2134752*||r_m||^2   (log2 domain)
// e = exp2(logit - rowmax);  z_v = sum_m e*r_m / sum_m e

#define TPB   128   // 4 warps/block, 2 tiles (32 vectors) per warp
#define DVEC  16

// Packed fp16 codebook tables. uint4 = {hi01, hi89, lo01, lo89}
__device__ uint4  gP1[256];   // pass-1 B: idx = m*4+q, k-slots (2q,2q+1)<-phys(4q,4q+1), (2q+8,2q+9)<-(4q+2,4q+3)
__device__ uint4  gPB[256];   // pass-2 B: idx = ((s*2+nt)*8+g)*4+q, output col J(g,nt)=4*(g>>1)+2*nt+(g&1)
__device__ float2 gB2[32];    // bias: idx = t*4+q -> {b2[8t+2q], b2[8t+2q+1]}

__device__ __forceinline__ uint32_t pkhf(float lo_elem, float hi_elem) {
    uint32_t r;
    asm("cvt.rn.f16x2.f32 %0, %1, %2;" : "=r"(r) : "f"(hi_elem), "f"(lo_elem));
    return r;
}
__device__ __forceinline__ float hf0(uint32_t u) {
    float f;
    asm("{ .reg .b16 l, h; mov.b32 {l, h}, %1; cvt.f32.f16 %0, l; }" : "=f"(f) : "r"(u));
    return f;
}
__device__ __forceinline__ float hf1(uint32_t u) {
    float f;
    asm("{ .reg .b16 l, h; mov.b32 {l, h}, %1; cvt.f32.f16 %0, h; }" : "=f"(f) : "r"(u));
    return f;
}
__device__ __forceinline__ float ex2f(float x) {
    float r; asm("ex2.approx.ftz.f32 %0, %1;" : "=f"(r) : "f"(x)); return r;
}
__device__ __forceinline__ float rcpf(float x) {
    float r; asm("rcp.approx.ftz.f32 %0, %1;" : "=f"(r) : "f"(x)); return r;
}
__device__ __forceinline__ void mma16(float c[4],
                                      uint32_t a0, uint32_t a1, uint32_t a2, uint32_t a3,
                                      uint32_t b0, uint32_t b1) {
    asm volatile(
        "mma.sync.aligned.m16n8k16.row.col.f32.f16.f16.f32 "
        "{%0,%1,%2,%3}, {%4,%5,%6,%7}, {%8,%9}, {%0,%1,%2,%3};"
        : "+f"(c[0]), "+f"(c[1]), "+f"(c[2]), "+f"(c[3])
        : "r"(a0), "r"(a1), "r"(a2), "r"(a3), "r"(b0), "r"(b1));
}
__device__ __forceinline__ uint4 split4(float v0, float v1, float v2, float v3) {
    uint4 r;
    r.x = pkhf(v0, v1);
    r.y = pkhf(v2, v3);
    r.z = pkhf(v0 - hf0(r.x), v1 - hf1(r.x));
    r.w = pkhf(v2 - hf0(r.y), v3 - hf1(r.y));
    return r;
}

__global__ void prep_kernel(const float* __restrict__ ref) {
    const int tid = threadIdx.x;  // 256 threads
    {   // Pass-1 B table: (m, q). k-slot permutation: slots {2q,2q+1,2q+8,2q+9}
        // hold physical k {4q,4q+1,4q+2,4q+3} (matches float4 x loads).
        const int m = tid >> 2, q = tid & 3;
        const float S = 14.426950408889634f;   // 10*log2(e)
        const float* b = ref + m * DVEC;
        gP1[tid] = split4(S * b[4 * q], S * b[4 * q + 1],
                          S * b[4 * q + 2], S * b[4 * q + 3]);
    }
    {   // Pass-2 B table: (s, nt, g, q). Output column J(g,nt) so each thread's
        // 4 outputs per row land at physical cols 4q..4q+3 (float4 stores).
        const int q = tid & 3, g = (tid >> 2) & 7, nt = (tid >> 5) & 1, s = tid >> 6;
        const int j = 4 * (g >> 1) + 2 * nt + (g & 1);
        gPB[tid] = split4(ref[(16 * s + 2 * q) * DVEC + j],
                          ref[(16 * s + 2 * q + 1) * DVEC + j],
                          ref[(16 * s + 2 * q + 8) * DVEC + j],
                          ref[(16 * s + 2 * q + 9) * DVEC + j]);
    }
    if (tid < 32) {  // bias pairs: (t, q)
        const int t = tid >> 2, q = tid & 3;
        const int m0 = 8 * t + 2 * q, m1 = m0 + 1;
        float s0 = 0.0f, s1 = 0.0f;
        #pragma unroll
        for (int i = 0; i < DVEC; i++) {
            s0 = fmaf(ref[m0 * DVEC + i], ref[m0 * DVEC + i], s0);
            s1 = fmaf(ref[m1 * DVEC + i], ref[m1 * DVEC + i], s1);
        }
        gB2[tid] = make_float2(-7.2134752044448169f * s0,
                               -7.2134752044448169f * s1);
    }
}

__global__ __launch_bounds__(TPB, 5)
void stq_kernel(const float* __restrict__ x, float* __restrict__ out) {
    __shared__ __align__(16) uint4 sP1[256];
    __shared__ __align__(16) uint4 sPB[256];
    __shared__ float2 sB2[32];

    const int tid = threadIdx.x;
    #pragma unroll
    for (int i = tid; i < 256; i += TPB) { sP1[i] = gP1[i]; sPB[i] = gPB[i]; }
    if (tid < 32) sB2[tid] = gB2[tid];
    __syncthreads();

    const int warp = tid >> 5;
    const int lane = tid & 31;
    const int g = lane >> 2;     // groupID
    const int q = lane & 3;      // threadID in group

    const int tp = (blockIdx.x * 4 + warp) * 2;   // tile pair base
    const int vA  = tp * 16 + g;
    const int vA8 = vA + 8;
    const int vB  = vA + 16;
    const int vB8 = vB + 8;

    // ---- Load + split pass-1 A fragments: ONE float4 per row (k-permuted) ----
    uint32_t ahA[4], alA[4], ahB[4], alB[4];
    {
        const float4 fA0 = *reinterpret_cast<const float4*>(x + (size_t)vA  * DVEC + 4 * q);
        const float4 fA1 = *reinterpret_cast<const float4*>(x + (size_t)vA8 * DVEC + 4 * q);
        ahA[0] = pkhf(fA0.x, fA0.y); alA[0] = pkhf(fA0.x - hf0(ahA[0]), fA0.y - hf1(ahA[0]));
        ahA[2] = pkhf(fA0.z, fA0.w); alA[2] = pkhf(fA0.z - hf0(ahA[2]), fA0.w - hf1(ahA[2]));
        ahA[1] = pkhf(fA1.x, fA1.y); alA[1] = pkhf(fA1.x - hf0(ahA[1]), fA1.y - hf1(ahA[1]));
        ahA[3] = pkhf(fA1.z, fA1.w); alA[3] = pkhf(fA1.z - hf0(ahA[3]), fA1.w - hf1(ahA[3]));
        const float4 fB0 = *reinterpret_cast<const float4*>(x + (size_t)vB  * DVEC + 4 * q);
        const float4 fB1 = *reinterpret_cast<const float4*>(x + (size_t)vB8 * DVEC + 4 * q);
        ahB[0] = pkhf(fB0.x, fB0.y); alB[0] = pkhf(fB0.x - hf0(ahB[0]), fB0.y - hf1(ahB[0]));
        ahB[2] = pkhf(fB0.z, fB0.w); alB[2] = pkhf(fB0.z - hf0(ahB[2]), fB0.w - hf1(ahB[2]));
        ahB[1] = pkhf(fB1.x, fB1.y); alB[1] = pkhf(fB1.x - hf0(ahB[1]), fB1.y - hf1(ahB[1]));
        ahB[3] = pkhf(fB1.z, fB1.w); alB[3] = pkhf(fB1.z - hf0(ahB[3]), fB1.w - hf1(ahB[3]));
    }

    // ---- Pass 1: logits; bias pre-loaded into accumulators ----
    float cA[8][4], cB[8][4];
    #pragma unroll
    for (int t = 0; t < 8; t++) {
        float2 bb = sB2[t * 4 + q];
        cA[t][0] = bb.x; cA[t][1] = bb.y; cA[t][2] = bb.x; cA[t][3] = bb.y;
        cB[t][0] = bb.x; cB[t][1] = bb.y; cB[t][2] = bb.x; cB[t][3] = bb.y;
    }
    #pragma unroll
    for (int t = 0; t < 8; t++) {
        uint4 P = sP1[(8 * t + g) * 4 + q];
        mma16(cA[t], ahA[0], ahA[1], ahA[2], ahA[3], P.x, P.y);
        mma16(cA[t], ahA[0], ahA[1], ahA[2], ahA[3], P.z, P.w);
        mma16(cA[t], alA[0], alA[1], alA[2], alA[3], P.x, P.y);
        mma16(cB[t], ahB[0], ahB[1], ahB[2], ahB[3], P.x, P.y);
        mma16(cB[t], ahB[0], ahB[1], ahB[2], ahB[3], P.z, P.w);
        mma16(cB[t], alB[0], alB[1], alB[2], alB[3], P.x, P.y);
    }

    // ---- row maxes ----
    float mgA = fmaxf(cA[0][0], cA[0][1]), m8A = fmaxf(cA[0][2], cA[0][3]);
    float mgB = fmaxf(cB[0][0], cB[0][1]), m8B = fmaxf(cB[0][2], cB[0][3]);
    #pragma unroll
    for (int t = 1; t < 8; t++) {
        mgA = fmaxf(mgA, fmaxf(cA[t][0], cA[t][1]));
        m8A = fmaxf(m8A, fmaxf(cA[t][2], cA[t][3]));
        mgB = fmaxf(mgB, fmaxf(cB[t][0], cB[t][1]));
        m8B = fmaxf(m8B, fmaxf(cB[t][2], cB[t][3]));
    }
    mgA = fmaxf(mgA, __shfl_xor_sync(0xffffffffu, mgA, 1));
    mgA = fmaxf(mgA, __shfl_xor_sync(0xffffffffu, mgA, 2));
    m8A = fmaxf(m8A, __shfl_xor_sync(0xffffffffu, m8A, 1));
    m8A = fmaxf(m8A, __shfl_xor_sync(0xffffffffu, m8A, 2));
    mgB = fmaxf(mgB, __shfl_xor_sync(0xffffffffu, mgB, 1));
    mgB = fmaxf(mgB, __shfl_xor_sync(0xffffffffu, mgB, 2));
    m8B = fmaxf(m8B, __shfl_xor_sync(0xffffffffu, m8B, 1));
    m8B = fmaxf(m8B, __shfl_xor_sync(0xffffffffu, m8B, 2));

    // ---- Pass 2: exp -> fp16 ONCE; z MMAs + ones-column MMA for denominator ----
    float zA[2][4], zB[2][4], wA[4], wB[4];
    #pragma unroll
    for (int nt = 0; nt < 2; nt++) {
        zA[nt][0] = zA[nt][1] = zA[nt][2] = zA[nt][3] = 0.0f;
        zB[nt][0] = zB[nt][1] = zB[nt][2] = zB[nt][3] = 0.0f;
    }
    wA[0] = wA[1] = wA[2] = wA[3] = 0.0f;
    wB[0] = wB[1] = wB[2] = wB[3] = 0.0f;
    const uint32_t onesb = (g == 0) ? 0x3C003C00u : 0u;   // fp16 1.0 pair on n=0 col

    #pragma unroll
    for (int s = 0; s < 4; s++) {
        uint32_t a0h = pkhf(ex2f(cA[2*s][0]   - mgA), ex2f(cA[2*s][1]   - mgA));
        uint32_t a1h = pkhf(ex2f(cA[2*s][2]   - m8A), ex2f(cA[2*s][3]   - m8A));
        uint32_t a2h = pkhf(ex2f(cA[2*s+1][0] - mgA), ex2f(cA[2*s+1][1] - mgA));
        uint32_t a3h = pkhf(ex2f(cA[2*s+1][2] - m8A), ex2f(cA[2*s+1][3] - m8A));
        uint32_t b0h = pkhf(ex2f(cB[2*s][0]   - mgB), ex2f(cB[2*s][1]   - mgB));
        uint32_t b1h = pkhf(ex2f(cB[2*s][2]   - m8B), ex2f(cB[2*s][3]   - m8B));
        uint32_t b2h = pkhf(ex2f(cB[2*s+1][0] - mgB), ex2f(cB[2*s+1][1] - mgB));
        uint32_t b3h = pkhf(ex2f(cB[2*s+1][2] - m8B), ex2f(cB[2*s+1][3] - m8B));

        // denominator: C[row][0] += sum_k e_hat[row][k] (exact f32 sum of the
        // SAME rounded weights -> consistent softmax)
        mma16(wA, a0h, a1h, a2h, a3h, onesb, onesb);
        mma16(wB, b0h, b1h, b2h, b3h, onesb, onesb);

        #pragma unroll
        for (int nt = 0; nt < 2; nt++) {
            uint4 P = sPB[((s * 2 + nt) * 8 + g) * 4 + q];
            mma16(zA[nt], a0h, a1h, a2h, a3h, P.x, P.y);
            mma16(zA[nt], a0h, a1h, a2h, a3h, P.z, P.w);
            mma16(zB[nt], b0h, b1h, b2h, b3h, P.x, P.y);
            mma16(zB[nt], b0h, b1h, b2h, b3h, P.z, P.w);
        }
    }

    // ---- broadcast denominators from q=0 (col 0) across each quad ----
    const int base = lane & 28;
    const float igA = rcpf(__shfl_sync(0xffffffffu, wA[0], base));
    const float i8A = rcpf(__shfl_sync(0xffffffffu, wA[2], base));
    const float igB = rcpf(__shfl_sync(0xffffffffu, wB[0], base));
    const float i8B = rcpf(__shfl_sync(0xffffffffu, wB[2], base));

    // ---- normalize + float4 stores (output-permuted: cols 4q..4q+3) ----
    *reinterpret_cast<float4*>(out + (size_t)vA  * DVEC + 4 * q) =
        make_float4(zA[0][0] * igA, zA[0][1] * igA, zA[1][0] * igA, zA[1][1] * igA);
    *reinterpret_cast<float4*>(out + (size_t)vA8 * DVEC + 4 * q) =
        make_float4(zA[0][2] * i8A, zA[0][3] * i8A, zA[1][2] * i8A, zA[1][3] * i8A);
    *reinterpret_cast<float4*>(out + (size_t)vB  * DVEC + 4 * q) =
        make_float4(zB[0][0] * igB, zB[0][1] * igB, zB[1][0] * igB, zB[1][1] * igB);
    *reinterpret_cast<float4*>(out + (size_t)vB8 * DVEC + 4 * q) =
        make_float4(zB[0][2] * i8B, zB[0][3] * i8B, zB[1][2] * i8B, zB[1][3] * i8B);
}

extern "C" void kernel_launch(void* const* d_in, const int* in_sizes, int n_in,
                              void* d_out, int out_size) {
    const float* x   = (const float*)d_in[0];   // (64,8,32,32,16) f32
    const float* ref = (const float*)d_in[1];   // (64,16) f32
    float* out = (float*)d_out;

    prep_kernel<<<1, 256>>>(ref);

    const int nvec = in_sizes[0] / DVEC;        // 524288
    const int tiles = nvec / 16;                // 32768
    const int blocks = tiles / 8;               // 4096 (4 warps x 2 tiles)
    stq_kernel<<<blocks, TPB>>>(x, out);
}

// round 14
// speedup vs baseline: 1.0983x; 1.0983x over previous
#include <cuda_runtime.h>
#include <cstdint>

// soft_to_hard_quantize via fp16 tensor cores (mma.m16n8k16).
// R14 vs R13: SINGLE LAUNCH — the codebook prep (scale/split/permute tables)
// is computed per-block in shared memory directly from ref, eliminating the
// separate prep kernel whose launch + graph gap cost ~4-6us per replay.
// Kernel body identical to R13 (best measured kernel: 21.6us).
//
// logit[v][m] = 14.4269504*dot(x_v, r_m) - 7.2134752*||r_m||^2   (log2 domain)
// e = exp2(logit - rowmax);  z_v = sum_m e*r_m / sum_m e

#define TPB   128   // 4 warps/block, 2 tiles (32 vectors) per warp
#define DVEC  16

__device__ __forceinline__ uint32_t pkhf(float lo_elem, float hi_elem) {
    uint32_t r;
    asm("cvt.rn.f16x2.f32 %0, %1, %2;" : "=r"(r) : "f"(hi_elem), "f"(lo_elem));
    return r;
}
__device__ __forceinline__ float hf0(uint32_t u) {
    float f;
    asm("{ .reg .b16 l, h; mov.b32 {l, h}, %1; cvt.f32.f16 %0, l; }" : "=f"(f) : "r"(u));
    return f;
}
__device__ __forceinline__ float hf1(uint32_t u) {
    float f;
    asm("{ .reg .b16 l, h; mov.b32 {l, h}, %1; cvt.f32.f16 %0, h; }" : "=f"(f) : "r"(u));
    return f;
}
__device__ __forceinline__ float ex2f(float x) {
    float r; asm("ex2.approx.ftz.f32 %0, %1;" : "=f"(r) : "f"(x)); return r;
}
__device__ __forceinline__ float rcpf(float x) {
    float r; asm("rcp.approx.ftz.f32 %0, %1;" : "=f"(r) : "f"(x)); return r;
}
__device__ __forceinline__ void mma16(float c[4],
                                      uint32_t a0, uint32_t a1, uint32_t a2, uint32_t a3,
                                      uint32_t b0, uint32_t b1) {
    asm volatile(
        "mma.sync.aligned.m16n8k16.row.col.f32.f16.f16.f32 "
        "{%0,%1,%2,%3}, {%4,%5,%6,%7}, {%8,%9}, {%0,%1,%2,%3};"
        : "+f"(c[0]), "+f"(c[1]), "+f"(c[2]), "+f"(c[3])
        : "r"(a0), "r"(a1), "r"(a2), "r"(a3), "r"(b0), "r"(b1));
}
__device__ __forceinline__ uint4 split4(float v0, float v1, float v2, float v3) {
    uint4 r;
    r.x = pkhf(v0, v1);
    r.y = pkhf(v2, v3);
    r.z = pkhf(v0 - hf0(r.x), v1 - hf1(r.x));
    r.w = pkhf(v2 - hf0(r.y), v3 - hf1(r.y));
    return r;
}

__global__ __launch_bounds__(TPB, 5)
void stq_kernel(const float* __restrict__ x,
                const float* __restrict__ ref,
                float* __restrict__ out) {
    // Codebook tables built in-block from ref (ref is 4KB, L2-resident).
    // sP1: pass-1 B, idx m*4+q; k-slots {2q,2q+1,2q+8,2q+9} <- phys {4q..4q+3}
    // sPB: pass-2 B, idx ((s*2+nt)*8+g)*4+q; output col J(g,nt)=4*(g>>1)+2*nt+(g&1)
    // sB2: bias pairs, idx t*4+q -> {b2[8t+2q], b2[8t+2q+1]}
    __shared__ __align__(16) uint4 sP1[256];
    __shared__ __align__(16) uint4 sPB[256];
    __shared__ float2 sB2[32];

    const int tid = threadIdx.x;

    #pragma unroll
    for (int i = tid; i < 256; i += TPB) {
        {   // pass-1 entry (m, qq)
            const int m = i >> 2, qq = i & 3;
            const float S = 14.426950408889634f;   // 10*log2(e)
            const float4 b = *reinterpret_cast<const float4*>(ref + m * DVEC + 4 * qq);
            sP1[i] = split4(S * b.x, S * b.y, S * b.z, S * b.w);
        }
        {   // pass-2 entry (s, nt, gg, qq)
            const int qq = i & 3, gg = (i >> 2) & 7, nt = (i >> 5) & 1, s = i >> 6;
            const int j = 4 * (gg >> 1) + 2 * nt + (gg & 1);
            sPB[i] = split4(ref[(16 * s + 2 * qq) * DVEC + j],
                            ref[(16 * s + 2 * qq + 1) * DVEC + j],
                            ref[(16 * s + 2 * qq + 8) * DVEC + j],
                            ref[(16 * s + 2 * qq + 9) * DVEC + j]);
        }
    }
    if (tid < 32) {  // bias pairs (t, qq)
        const int t = tid >> 2, qq = tid & 3;
        const int m0 = 8 * t + 2 * qq, m1 = m0 + 1;
        float s0 = 0.0f, s1 = 0.0f;
        #pragma unroll
        for (int i = 0; i < DVEC; i += 4) {
            const float4 a = *reinterpret_cast<const float4*>(ref + m0 * DVEC + i);
            const float4 b = *reinterpret_cast<const float4*>(ref + m1 * DVEC + i);
            s0 = fmaf(a.x, a.x, fmaf(a.y, a.y, fmaf(a.z, a.z, fmaf(a.w, a.w, s0))));
            s1 = fmaf(b.x, b.x, fmaf(b.y, b.y, fmaf(b.z, b.z, fmaf(b.w, b.w, s1))));
        }
        sB2[tid] = make_float2(-7.2134752044448169f * s0,
                               -7.2134752044448169f * s1);
    }
    __syncthreads();

    const int warp = tid >> 5;
    const int lane = tid & 31;
    const int g = lane >> 2;     // groupID
    const int q = lane & 3;      // threadID in group

    const int tp = (blockIdx.x * 4 + warp) * 2;   // tile pair base
    const int vA  = tp * 16 + g;
    const int vA8 = vA + 8;
    const int vB  = vA + 16;
    const int vB8 = vB + 8;

    // ---- Load + split pass-1 A fragments: ONE float4 per row (k-permuted) ----
    uint32_t ahA[4], alA[4], ahB[4], alB[4];
    {
        const float4 fA0 = *reinterpret_cast<const float4*>(x + (size_t)vA  * DVEC + 4 * q);
        const float4 fA1 = *reinterpret_cast<const float4*>(x + (size_t)vA8 * DVEC + 4 * q);
        ahA[0] = pkhf(fA0.x, fA0.y); alA[0] = pkhf(fA0.x - hf0(ahA[0]), fA0.y - hf1(ahA[0]));
        ahA[2] = pkhf(fA0.z, fA0.w); alA[2] = pkhf(fA0.z - hf0(ahA[2]), fA0.w - hf1(ahA[2]));
        ahA[1] = pkhf(fA1.x, fA1.y); alA[1] = pkhf(fA1.x - hf0(ahA[1]), fA1.y - hf1(ahA[1]));
        ahA[3] = pkhf(fA1.z, fA1.w); alA[3] = pkhf(fA1.z - hf0(ahA[3]), fA1.w - hf1(ahA[3]));
        const float4 fB0 = *reinterpret_cast<const float4*>(x + (size_t)vB  * DVEC + 4 * q);
        const float4 fB1 = *reinterpret_cast<const float4*>(x + (size_t)vB8 * DVEC + 4 * q);
        ahB[0] = pkhf(fB0.x, fB0.y); alB[0] = pkhf(fB0.x - hf0(ahB[0]), fB0.y - hf1(ahB[0]));
        ahB[2] = pkhf(fB0.z, fB0.w); alB[2] = pkhf(fB0.z - hf0(ahB[2]), fB0.w - hf1(ahB[2]));
        ahB[1] = pkhf(fB1.x, fB1.y); alB[1] = pkhf(fB1.x - hf0(ahB[1]), fB1.y - hf1(ahB[1]));
        ahB[3] = pkhf(fB1.z, fB1.w); alB[3] = pkhf(fB1.z - hf0(ahB[3]), fB1.w - hf1(ahB[3]));
    }

    // ---- Pass 1: logits; bias pre-loaded into accumulators ----
    float cA[8][4], cB[8][4];
    #pragma unroll
    for (int t = 0; t < 8; t++) {
        float2 bb = sB2[t * 4 + q];
        cA[t][0] = bb.x; cA[t][1] = bb.y; cA[t][2] = bb.x; cA[t][3] = bb.y;
        cB[t][0] = bb.x; cB[t][1] = bb.y; cB[t][2] = bb.x; cB[t][3] = bb.y;
    }
    #pragma unroll
    for (int t = 0; t < 8; t++) {
        uint4 P = sP1[(8 * t + g) * 4 + q];
        mma16(cA[t], ahA[0], ahA[1], ahA[2], ahA[3], P.x, P.y);
        mma16(cA[t], ahA[0], ahA[1], ahA[2], ahA[3], P.z, P.w);
        mma16(cA[t], alA[0], alA[1], alA[2], alA[3], P.x, P.y);
        mma16(cB[t], ahB[0], ahB[1], ahB[2], ahB[3], P.x, P.y);
        mma16(cB[t], ahB[0], ahB[1], ahB[2], ahB[3], P.z, P.w);
        mma16(cB[t], alB[0], alB[1], alB[2], alB[3], P.x, P.y);
    }

    // ---- row maxes ----
    float mgA = fmaxf(cA[0][0], cA[0][1]), m8A = fmaxf(cA[0][2], cA[0][3]);
    float mgB = fmaxf(cB[0][0], cB[0][1]), m8B = fmaxf(cB[0][2], cB[0][3]);
    #pragma unroll
    for (int t = 1; t < 8; t++) {
        mgA = fmaxf(mgA, fmaxf(cA[t][0], cA[t][1]));
        m8A = fmaxf(m8A, fmaxf(cA[t][2], cA[t][3]));
        mgB = fmaxf(mgB, fmaxf(cB[t][0], cB[t][1]));
        m8B = fmaxf(m8B, fmaxf(cB[t][2], cB[t][3]));
    }
    mgA = fmaxf(mgA, __shfl_xor_sync(0xffffffffu, mgA, 1));
    mgA = fmaxf(mgA, __shfl_xor_sync(0xffffffffu, mgA, 2));
    m8A = fmaxf(m8A, __shfl_xor_sync(0xffffffffu, m8A, 1));
    m8A = fmaxf(m8A, __shfl_xor_sync(0xffffffffu, m8A, 2));
    mgB = fmaxf(mgB, __shfl_xor_sync(0xffffffffu, mgB, 1));
    mgB = fmaxf(mgB, __shfl_xor_sync(0xffffffffu, mgB, 2));
    m8B = fmaxf(m8B, __shfl_xor_sync(0xffffffffu, m8B, 1));
    m8B = fmaxf(m8B, __shfl_xor_sync(0xffffffffu, m8B, 2));

    // ---- Pass 2: exp -> fp16 ONCE; z MMAs + ones-column MMA for denominator ----
    float zA[2][4], zB[2][4], wA[4], wB[4];
    #pragma unroll
    for (int nt = 0; nt < 2; nt++) {
        zA[nt][0] = zA[nt][1] = zA[nt][2] = zA[nt][3] = 0.0f;
        zB[nt][0] = zB[nt][1] = zB[nt][2] = zB[nt][3] = 0.0f;
    }
    wA[0] = wA[1] = wA[2] = wA[3] = 0.0f;
    wB[0] = wB[1] = wB[2] = wB[3] = 0.0f;
    const uint32_t onesb = (g == 0) ? 0x3C003C00u : 0u;   // fp16 1.0 pair on n=0 col

    #pragma unroll
    for (int s = 0; s < 4; s++) {
        uint32_t a0h = pkhf(ex2f(cA[2*s][0]   - mgA), ex2f(cA[2*s][1]   - mgA));
        uint32_t a1h = pkhf(ex2f(cA[2*s][2]   - m8A), ex2f(cA[2*s][3]   - m8A));
        uint32_t a2h = pkhf(ex2f(cA[2*s+1][0] - mgA), ex2f(cA[2*s+1][1] - mgA));
        uint32_t a3h = pkhf(ex2f(cA[2*s+1][2] - m8A), ex2f(cA[2*s+1][3] - m8A));
        uint32_t b0h = pkhf(ex2f(cB[2*s][0]   - mgB), ex2f(cB[2*s][1]   - mgB));
        uint32_t b1h = pkhf(ex2f(cB[2*s][2]   - m8B), ex2f(cB[2*s][3]   - m8B));
        uint32_t b2h = pkhf(ex2f(cB[2*s+1][0] - mgB), ex2f(cB[2*s+1][1] - mgB));
        uint32_t b3h = pkhf(ex2f(cB[2*s+1][2] - m8B), ex2f(cB[2*s+1][3] - m8B));

        // denominator: C[row][0] += sum_k e_hat[row][k]
        mma16(wA, a0h, a1h, a2h, a3h, onesb, onesb);
        mma16(wB, b0h, b1h, b2h, b3h, onesb, onesb);

        #pragma unroll
        for (int nt = 0; nt < 2; nt++) {
            uint4 P = sPB[((s * 2 + nt) * 8 + g) * 4 + q];
            mma16(zA[nt], a0h, a1h, a2h, a3h, P.x, P.y);
            mma16(zA[nt], a0h, a1h, a2h, a3h, P.z, P.w);
            mma16(zB[nt], b0h, b1h, b2h, b3h, P.x, P.y);
            mma16(zB[nt], b0h, b1h, b2h, b3h, P.z, P.w);
        }
    }

    // ---- broadcast denominators from q=0 (col 0) across each quad ----
    const int base = lane & 28;
    const float igA = rcpf(__shfl_sync(0xffffffffu, wA[0], base));
    const float i8A = rcpf(__shfl_sync(0xffffffffu, wA[2], base));
    const float igB = rcpf(__shfl_sync(0xffffffffu, wB[0], base));
    const float i8B = rcpf(__shfl_sync(0xffffffffu, wB[2], base));

    // ---- normalize + float4 stores (output-permuted: cols 4q..4q+3) ----
    *reinterpret_cast<float4*>(out + (size_t)vA  * DVEC + 4 * q) =
        make_float4(zA[0][0] * igA, zA[0][1] * igA, zA[1][0] * igA, zA[1][1] * igA);
    *reinterpret_cast<float4*>(out + (size_t)vA8 * DVEC + 4 * q) =
        make_float4(zA[0][2] * i8A, zA[0][3] * i8A, zA[1][2] * i8A, zA[1][3] * i8A);
    *reinterpret_cast<float4*>(out + (size_t)vB  * DVEC + 4 * q) =
        make_float4(zB[0][0] * igB, zB[0][1] * igB, zB[1][0] * igB, zB[1][1] * igB);
    *reinterpret_cast<float4*>(out + (size_t)vB8 * DVEC + 4 * q) =
        make_float4(zB[0][2] * i8B, zB[0][3] * i8B, zB[1][2] * i8B, zB[1][3] * i8B);
}

extern "C" void kernel_launch(void* const* d_in, const int* in_sizes, int n_in,
                              void* d_out, int out_size) {
    const float* x   = (const float*)d_in[0];   // (64,8,32,32,16) f32
    const float* ref = (const float*)d_in[1];   // (64,16) f32
    float* out = (float*)d_out;

    const int nvec = in_sizes[0] / DVEC;        // 524288
    const int tiles = nvec / 16;                // 32768
    const int blocks = tiles / 8;               // 4096 (4 warps x 2 tiles)
    stq_kernel<<<blocks, TPB>>>(x, ref, out);
}

// round 15
// speedup vs baseline: 1.1846x; 1.0785x over previous
#include <cuda_runtime.h>
#include <cstdint>

// soft_to_hard_quantize via fp16 tensor cores (mma.m16n8k16).
// R15 vs R14: PERSISTENT blocks. One wave of 760 blocks (152 SM x 5 CTA), each
// builds the smem codebook tables ONCE and grid-strides over ~5.4 tile-pair
// chunks, amortizing the per-block prep that cost ~2.4us across 4096 blocks.
// Math identical to R13/R14 (fp16 3-term pass 1, consistent-fp16 2-term pass 2,
// ones-column MMA denominator, float4 IO via k/output permutations).
//
// logit[v][m] = 14.4269504*dot(x_v, r_m) - 7.2134752*||r_m||^2   (log2 domain)
// e = exp2(logit - rowmax);  z_v = sum_m e*r_m / sum_m e

#define TPB    128    // 4 warps/block, 2 tiles (32 vectors) per warp-iteration
#define DVEC   16
#define NCHUNK 4096   // tile-pair chunks (each chunk = 4 warps x 1 pair = 128 vec)
#define NBLK   760    // 152 SMs x 5 CTAs -> one resident wave

__device__ __forceinline__ uint32_t pkhf(float lo_elem, float hi_elem) {
    uint32_t r;
    asm("cvt.rn.f16x2.f32 %0, %1, %2;" : "=r"(r) : "f"(hi_elem), "f"(lo_elem));
    return r;
}
__device__ __forceinline__ float hf0(uint32_t u) {
    float f;
    asm("{ .reg .b16 l, h; mov.b32 {l, h}, %1; cvt.f32.f16 %0, l; }" : "=f"(f) : "r"(u));
    return f;
}
__device__ __forceinline__ float hf1(uint32_t u) {
    float f;
    asm("{ .reg .b16 l, h; mov.b32 {l, h}, %1; cvt.f32.f16 %0, h; }" : "=f"(f) : "r"(u));
    return f;
}
__device__ __forceinline__ float ex2f(float x) {
    float r; asm("ex2.approx.ftz.f32 %0, %1;" : "=f"(r) : "f"(x)); return r;
}
__device__ __forceinline__ float rcpf(float x) {
    float r; asm("rcp.approx.ftz.f32 %0, %1;" : "=f"(r) : "f"(x)); return r;
}
__device__ __forceinline__ void mma16(float c[4],
                                      uint32_t a0, uint32_t a1, uint32_t a2, uint32_t a3,
                                      uint32_t b0, uint32_t b1) {
    asm volatile(
        "mma.sync.aligned.m16n8k16.row.col.f32.f16.f16.f32 "
        "{%0,%1,%2,%3}, {%4,%5,%6,%7}, {%8,%9}, {%0,%1,%2,%3};"
        : "+f"(c[0]), "+f"(c[1]), "+f"(c[2]), "+f"(c[3])
        : "r"(a0), "r"(a1), "r"(a2), "r"(a3), "r"(b0), "r"(b1));
}
__device__ __forceinline__ uint4 split4(float v0, float v1, float v2, float v3) {
    uint4 r;
    r.x = pkhf(v0, v1);
    r.y = pkhf(v2, v3);
    r.z = pkhf(v0 - hf0(r.x), v1 - hf1(r.x));
    r.w = pkhf(v2 - hf0(r.y), v3 - hf1(r.y));
    return r;
}

__global__ __launch_bounds__(TPB, 5)
void stq_kernel(const float* __restrict__ x,
                const float* __restrict__ ref,
                float* __restrict__ out) {
    // Codebook tables, built ONCE per persistent block.
    // sP1: pass-1 B, idx m*4+q; k-slots {2q,2q+1,2q+8,2q+9} <- phys {4q..4q+3}
    // sPB: pass-2 B, idx ((s*2+nt)*8+g)*4+q; output col J(g,nt)=4*(g>>1)+2*nt+(g&1)
    // sB2: bias pairs, idx t*4+q -> {b2[8t+2q], b2[8t+2q+1]}
    __shared__ __align__(16) uint4 sP1[256];
    __shared__ __align__(16) uint4 sPB[256];
    __shared__ float2 sB2[32];

    const int tid = threadIdx.x;

    #pragma unroll
    for (int i = tid; i < 256; i += TPB) {
        {   // pass-1 entry (m, qq)
            const int m = i >> 2, qq = i & 3;
            const float S = 14.426950408889634f;   // 10*log2(e)
            const float4 b = *reinterpret_cast<const float4*>(ref + m * DVEC + 4 * qq);
            sP1[i] = split4(S * b.x, S * b.y, S * b.z, S * b.w);
        }
        {   // pass-2 entry (s, nt, gg, qq)
            const int qq = i & 3, gg = (i >> 2) & 7, nt = (i >> 5) & 1, s = i >> 6;
            const int j = 4 * (gg >> 1) + 2 * nt + (gg & 1);
            sPB[i] = split4(ref[(16 * s + 2 * qq) * DVEC + j],
                            ref[(16 * s + 2 * qq + 1) * DVEC + j],
                            ref[(16 * s + 2 * qq + 8) * DVEC + j],
                            ref[(16 * s + 2 * qq + 9) * DVEC + j]);
        }
    }
    if (tid < 32) {  // bias pairs (t, qq)
        const int t = tid >> 2, qq = tid & 3;
        const int m0 = 8 * t + 2 * qq, m1 = m0 + 1;
        float s0 = 0.0f, s1 = 0.0f;
        #pragma unroll
        for (int i = 0; i < DVEC; i += 4) {
            const float4 a = *reinterpret_cast<const float4*>(ref + m0 * DVEC + i);
            const float4 b = *reinterpret_cast<const float4*>(ref + m1 * DVEC + i);
            s0 = fmaf(a.x, a.x, fmaf(a.y, a.y, fmaf(a.z, a.z, fmaf(a.w, a.w, s0))));
            s1 = fmaf(b.x, b.x, fmaf(b.y, b.y, fmaf(b.z, b.z, fmaf(b.w, b.w, s1))));
        }
        sB2[tid] = make_float2(-7.2134752044448169f * s0,
                               -7.2134752044448169f * s1);
    }
    __syncthreads();

    const int warp = tid >> 5;
    const int lane = tid & 31;
    const int g = lane >> 2;     // groupID
    const int q = lane & 3;      // threadID in group
    const int base = lane & 28;
    const uint32_t onesb = (g == 0) ? 0x3C003C00u : 0u;   // fp16 1.0 pair, n=0 col

    // ---- persistent grid-stride loop over tile-pair chunks ----
    for (int chunk = blockIdx.x; chunk < NCHUNK; chunk += NBLK) {
        const int tp = (chunk * 4 + warp) * 2;   // tile pair base
        const int vA  = tp * 16 + g;
        const int vA8 = vA + 8;
        const int vB  = vA + 16;
        const int vB8 = vB + 8;

        // ---- Load + split pass-1 A fragments: ONE float4 per row ----
        uint32_t ahA[4], alA[4], ahB[4], alB[4];
        {
            const float4 fA0 = *reinterpret_cast<const float4*>(x + (size_t)vA  * DVEC + 4 * q);
            const float4 fA1 = *reinterpret_cast<const float4*>(x + (size_t)vA8 * DVEC + 4 * q);
            ahA[0] = pkhf(fA0.x, fA0.y); alA[0] = pkhf(fA0.x - hf0(ahA[0]), fA0.y - hf1(ahA[0]));
            ahA[2] = pkhf(fA0.z, fA0.w); alA[2] = pkhf(fA0.z - hf0(ahA[2]), fA0.w - hf1(ahA[2]));
            ahA[1] = pkhf(fA1.x, fA1.y); alA[1] = pkhf(fA1.x - hf0(ahA[1]), fA1.y - hf1(ahA[1]));
            ahA[3] = pkhf(fA1.z, fA1.w); alA[3] = pkhf(fA1.z - hf0(ahA[3]), fA1.w - hf1(ahA[3]));
            const float4 fB0 = *reinterpret_cast<const float4*>(x + (size_t)vB  * DVEC + 4 * q);
            const float4 fB1 = *reinterpret_cast<const float4*>(x + (size_t)vB8 * DVEC + 4 * q);
            ahB[0] = pkhf(fB0.x, fB0.y); alB[0] = pkhf(fB0.x - hf0(ahB[0]), fB0.y - hf1(ahB[0]));
            ahB[2] = pkhf(fB0.z, fB0.w); alB[2] = pkhf(fB0.z - hf0(ahB[2]), fB0.w - hf1(ahB[2]));
            ahB[1] = pkhf(fB1.x, fB1.y); alB[1] = pkhf(fB1.x - hf0(ahB[1]), fB1.y - hf1(ahB[1]));
            ahB[3] = pkhf(fB1.z, fB1.w); alB[3] = pkhf(fB1.z - hf0(ahB[3]), fB1.w - hf1(ahB[3]));
        }

        // ---- Pass 1: logits; bias pre-loaded into accumulators ----
        float cA[8][4], cB[8][4];
        #pragma unroll
        for (int t = 0; t < 8; t++) {
            float2 bb = sB2[t * 4 + q];
            cA[t][0] = bb.x; cA[t][1] = bb.y; cA[t][2] = bb.x; cA[t][3] = bb.y;
            cB[t][0] = bb.x; cB[t][1] = bb.y; cB[t][2] = bb.x; cB[t][3] = bb.y;
        }
        #pragma unroll
        for (int t = 0; t < 8; t++) {
            uint4 P = sP1[(8 * t + g) * 4 + q];
            mma16(cA[t], ahA[0], ahA[1], ahA[2], ahA[3], P.x, P.y);
            mma16(cA[t], ahA[0], ahA[1], ahA[2], ahA[3], P.z, P.w);
            mma16(cA[t], alA[0], alA[1], alA[2], alA[3], P.x, P.y);
            mma16(cB[t], ahB[0], ahB[1], ahB[2], ahB[3], P.x, P.y);
            mma16(cB[t], ahB[0], ahB[1], ahB[2], ahB[3], P.z, P.w);
            mma16(cB[t], alB[0], alB[1], alB[2], alB[3], P.x, P.y);
        }

        // ---- row maxes ----
        float mgA = fmaxf(cA[0][0], cA[0][1]), m8A = fmaxf(cA[0][2], cA[0][3]);
        float mgB = fmaxf(cB[0][0], cB[0][1]), m8B = fmaxf(cB[0][2], cB[0][3]);
        #pragma unroll
        for (int t = 1; t < 8; t++) {
            mgA = fmaxf(mgA, fmaxf(cA[t][0], cA[t][1]));
            m8A = fmaxf(m8A, fmaxf(cA[t][2], cA[t][3]));
            mgB = fmaxf(mgB, fmaxf(cB[t][0], cB[t][1]));
            m8B = fmaxf(m8B, fmaxf(cB[t][2], cB[t][3]));
        }
        mgA = fmaxf(mgA, __shfl_xor_sync(0xffffffffu, mgA, 1));
        mgA = fmaxf(mgA, __shfl_xor_sync(0xffffffffu, mgA, 2));
        m8A = fmaxf(m8A, __shfl_xor_sync(0xffffffffu, m8A, 1));
        m8A = fmaxf(m8A, __shfl_xor_sync(0xffffffffu, m8A, 2));
        mgB = fmaxf(mgB, __shfl_xor_sync(0xffffffffu, mgB, 1));
        mgB = fmaxf(mgB, __shfl_xor_sync(0xffffffffu, mgB, 2));
        m8B = fmaxf(m8B, __shfl_xor_sync(0xffffffffu, m8B, 1));
        m8B = fmaxf(m8B, __shfl_xor_sync(0xffffffffu, m8B, 2));

        // ---- Pass 2: exp -> fp16 ONCE; z MMAs + ones-column denominator ----
        float zA[2][4], zB[2][4], wA[4], wB[4];
        #pragma unroll
        for (int nt = 0; nt < 2; nt++) {
            zA[nt][0] = zA[nt][1] = zA[nt][2] = zA[nt][3] = 0.0f;
            zB[nt][0] = zB[nt][1] = zB[nt][2] = zB[nt][3] = 0.0f;
        }
        wA[0] = wA[1] = wA[2] = wA[3] = 0.0f;
        wB[0] = wB[1] = wB[2] = wB[3] = 0.0f;

        #pragma unroll
        for (int s = 0; s < 4; s++) {
            uint32_t a0h = pkhf(ex2f(cA[2*s][0]   - mgA), ex2f(cA[2*s][1]   - mgA));
            uint32_t a1h = pkhf(ex2f(cA[2*s][2]   - m8A), ex2f(cA[2*s][3]   - m8A));
            uint32_t a2h = pkhf(ex2f(cA[2*s+1][0] - mgA), ex2f(cA[2*s+1][1] - mgA));
            uint32_t a3h = pkhf(ex2f(cA[2*s+1][2] - m8A), ex2f(cA[2*s+1][3] - m8A));
            uint32_t b0h = pkhf(ex2f(cB[2*s][0]   - mgB), ex2f(cB[2*s][1]   - mgB));
            uint32_t b1h = pkhf(ex2f(cB[2*s][2]   - m8B), ex2f(cB[2*s][3]   - m8B));
            uint32_t b2h = pkhf(ex2f(cB[2*s+1][0] - mgB), ex2f(cB[2*s+1][1] - mgB));
            uint32_t b3h = pkhf(ex2f(cB[2*s+1][2] - m8B), ex2f(cB[2*s+1][3] - m8B));

            mma16(wA, a0h, a1h, a2h, a3h, onesb, onesb);
            mma16(wB, b0h, b1h, b2h, b3h, onesb, onesb);

            #pragma unroll
            for (int nt = 0; nt < 2; nt++) {
                uint4 P = sPB[((s * 2 + nt) * 8 + g) * 4 + q];
                mma16(zA[nt], a0h, a1h, a2h, a3h, P.x, P.y);
                mma16(zA[nt], a0h, a1h, a2h, a3h, P.z, P.w);
                mma16(zB[nt], b0h, b1h, b2h, b3h, P.x, P.y);
                mma16(zB[nt], b0h, b1h, b2h, b3h, P.z, P.w);
            }
        }

        // ---- broadcast denominators from q=0 (col 0) across each quad ----
        const float igA = rcpf(__shfl_sync(0xffffffffu, wA[0], base));
        const float i8A = rcpf(__shfl_sync(0xffffffffu, wA[2], base));
        const float igB = rcpf(__shfl_sync(0xffffffffu, wB[0], base));
        const float i8B = rcpf(__shfl_sync(0xffffffffu, wB[2], base));

        // ---- normalize + float4 stores (output-permuted: cols 4q..4q+3) ----
        *reinterpret_cast<float4*>(out + (size_t)vA  * DVEC + 4 * q) =
            make_float4(zA[0][0] * igA, zA[0][1] * igA, zA[1][0] * igA, zA[1][1] * igA);
        *reinterpret_cast<float4*>(out + (size_t)vA8 * DVEC + 4 * q) =
            make_float4(zA[0][2] * i8A, zA[0][3] * i8A, zA[1][2] * i8A, zA[1][3] * i8A);
        *reinterpret_cast<float4*>(out + (size_t)vB  * DVEC + 4 * q) =
            make_float4(zB[0][0] * igB, zB[0][1] * igB, zB[1][0] * igB, zB[1][1] * igB);
        *reinterpret_cast<float4*>(out + (size_t)vB8 * DVEC + 4 * q) =
            make_float4(zB[0][2] * i8B, zB[0][3] * i8B, zB[1][2] * i8B, zB[1][3] * i8B);
    }
}

extern "C" void kernel_launch(void* const* d_in, const int* in_sizes, int n_in,
                              void* d_out, int out_size) {
    const float* x   = (const float*)d_in[0];   // (64,8,32,32,16) f32
    const float* ref = (const float*)d_in[1];   // (64,16) f32
    float* out = (float*)d_out;

    // NCHUNK * 128 vectors = 524288 = nvec (fixed shape per metadata).
    stq_kernel<<<NBLK, TPB>>>(x, ref, out);
}